// round 11
// baseline (speedup 1.0000x reference)
#include <cuda_runtime.h>

#define SEQ   1024
#define HID   512
#define GATES 2048
#define EMB   512
#define G_CTAS 128      // scan CTAs
#define UNITS_PER 4     // HID / G_CTAS == warps per scan CTA
#define SCAN_THREADS 128
#define NREP 8          // replicas of the tagged h stream
#define NBUF 8          // tagged ring depth (power of 2)

// ---------------- device scratch (static, no allocation) ----------------
__device__ float g_xg[SEQ * GATES];              // 8 MB precomputed input gates
// Tagged h stream: 64-bit word = {tag:32 | value:32}. Word for unit u of h_t
// lives at slot t&(NBUF-1), tag = t+1. Zeroed state = h_{-1} with tag 0.
// Zero-init at module load; re-zeroed by xgates_gemm every call.
__device__ unsigned long long g_hp[NBUF][NREP][HID];

__device__ __forceinline__ float fsigm(float x) {
    return 1.0f / (1.0f + __expf(-x));
}
__device__ __forceinline__ float ftanh(float x) {
    return 2.0f / (1.0f + __expf(-2.0f * x)) - 1.0f;
}

__device__ __forceinline__ unsigned long long ldg_strong(
    const unsigned long long* p) {
    unsigned long long v;
    asm volatile("ld.global.relaxed.gpu.b64 %0, [%1];"
                 : "=l"(v) : "l"(p) : "memory");
    return v;
}
__device__ __forceinline__ void stg_strong(unsigned long long* p,
                                           unsigned long long v) {
    asm volatile("st.global.relaxed.gpu.b64 [%0], %1;"
                 :: "l"(p), "l"(v) : "memory");
}

// ---------------- kernel 1: x_gates GEMM + ring re-init ------------------
// Also re-zeroes the tagged ring for the NEXT scan launch (first 128 blocks,
// one u64 per thread: 128*256 = 32768 = NBUF*NREP*HID words).
__global__ void __launch_bounds__(256) xgates_gemm(
    const int*   __restrict__ tok,
    const float* __restrict__ emb,
    const float* __restrict__ w_ih,
    const float* __restrict__ b_ih,
    const float* __restrict__ b_hh)
{
    __shared__ float As[32][68];
    __shared__ float Bs[32][68];
    __shared__ int   stok[64];

    const int tid = threadIdx.x;
    const int bm = blockIdx.y * 64;
    const int bn = blockIdx.x * 64;

    {   // ring re-init (module-load zeroing covers the very first call)
        int bid = blockIdx.y * gridDim.x + blockIdx.x;
        if (bid < 128)
            ((unsigned long long*)g_hp)[bid * 256 + tid] = 0ull;
    }

    if (tid < 64) stok[tid] = tok[bm + tid];
    __syncthreads();

    float acc[4][4];
    #pragma unroll
    for (int i = 0; i < 4; i++)
        #pragma unroll
        for (int j = 0; j < 4; j++) acc[i][j] = 0.0f;

    const int tr = tid >> 4;
    const int tc = tid & 15;

    for (int k0 = 0; k0 < EMB; k0 += 32) {
        #pragma unroll
        for (int i = 0; i < 2; i++) {
            int idx = tid + 256 * i;
            int row = idx & 63;
            int k4  = idx >> 6;
            float4 av = *reinterpret_cast<const float4*>(
                emb + (size_t)stok[row] * EMB + k0 + k4 * 4);
            As[k4*4+0][row] = av.x; As[k4*4+1][row] = av.y;
            As[k4*4+2][row] = av.z; As[k4*4+3][row] = av.w;
            float4 bv = *reinterpret_cast<const float4*>(
                w_ih + (size_t)(bn + row) * EMB + k0 + k4 * 4);
            Bs[k4*4+0][row] = bv.x; Bs[k4*4+1][row] = bv.y;
            Bs[k4*4+2][row] = bv.z; Bs[k4*4+3][row] = bv.w;
        }
        __syncthreads();

        #pragma unroll
        for (int kk = 0; kk < 32; kk++) {
            float4 a4 = *reinterpret_cast<const float4*>(&As[kk][tr * 4]);
            float4 b4 = *reinterpret_cast<const float4*>(&Bs[kk][tc * 4]);
            float a[4] = {a4.x, a4.y, a4.z, a4.w};
            float b[4] = {b4.x, b4.y, b4.z, b4.w};
            #pragma unroll
            for (int i = 0; i < 4; i++)
                #pragma unroll
                for (int j = 0; j < 4; j++)
                    acc[i][j] = fmaf(a[i], b[j], acc[i][j]);
        }
        __syncthreads();
    }

    const int gcol = bn + tc * 4;
    float4 bias;
    bias.x = b_ih[gcol + 0] + b_hh[gcol + 0];
    bias.y = b_ih[gcol + 1] + b_hh[gcol + 1];
    bias.z = b_ih[gcol + 2] + b_hh[gcol + 2];
    bias.w = b_ih[gcol + 3] + b_hh[gcol + 3];
    #pragma unroll
    for (int i = 0; i < 4; i++) {
        int trow = bm + tr * 4 + i;
        float4 v;
        v.x = acc[i][0] + bias.x;
        v.y = acc[i][1] + bias.y;
        v.z = acc[i][2] + bias.z;
        v.w = acc[i][3] + bias.w;
        *reinterpret_cast<float4*>(g_xg + (size_t)trow * GATES + gcol) = v;
    }
}

// ---------------- kernel 2: persistent LSTM scan + fused attention head --
// 128 CTAs x 128 threads; warp w (0..3) owns unit u = base + w. ONE
// __syncthreads per step. With 4 warps/CTA there is 1 warp per SMSP, so the
// 64-FMA gate matvec issues in ~128 cyc instead of ~256 (R10's 8 warps/CTA
// put 2 warps on each SMSP; ncu showed the scan latency-bound, and FMA issue
// serialization was the largest reducible term).
// Phase A: each thread polls its 4 contiguous tagged words (one 32B sector;
// 4 independent relaxed u64 loads pipeline -> detection granularity ~50 cyc).
// Tags are monotonic; any matching sample carries that tag's unique value.
// Safety/deadlock argument identical to R9 (sharding doesn't change the tag
// dependency order); NBUF=8 ring, zeroed before each scan by the GEMM.
__global__ void __launch_bounds__(SCAN_THREADS, 1) lstm_scan(
    const float* __restrict__ w_hh,
    const float* __restrict__ attn_w,
    const float* __restrict__ attn_b,
    float*       __restrict__ out)
{
    const int tid  = threadIdx.x;
    const int warp = tid >> 5;
    const int lane = tid & 31;
    const int base = blockIdx.x * UNITS_PER;
    const int unit = base + warp;
    const int rep  = blockIdx.x & (NREP - 1);

    // Weight rows for this warp's unit: gate q row = q*512 + unit.
    // Lane l holds k = l + 32m (conflict-free LDS of staged h).
    float w[4][16];
    #pragma unroll
    for (int q = 0; q < 4; q++) {
        const float* src = w_hh + (size_t)(q * HID + unit) * HID + lane;
        #pragma unroll
        for (int m = 0; m < 16; m++) w[q][m] = src[32 * m];
    }

    __shared__ float sh_h[2][HID];
    __shared__ float red[4];
    float c_state = 0.0f;

    for (int t = 0; t < SEQ; t++) {
        const unsigned tg = (unsigned)t;
        float* shb = sh_h[t & 1];

        // xg prefetch: warp-uniform addresses -> LDG broadcast; issued
        // before the poll so latency hides behind the spin.
        const float* xp = g_xg + (size_t)t * GATES + unit;
        float xg0 = __ldg(xp);
        float xg1 = __ldg(xp + 512);
        float xg2 = __ldg(xp + 1024);
        float xg3 = __ldg(xp + 1536);

        // Phase A: pipelined poll of 4 tagged words, stage values to smem.
        {
            const unsigned long long* gp =
                &g_hp[(t + NBUF - 1) & (NBUF - 1)][rep][tid * 4];
            unsigned done = 0u;                 // bit i = word i staged
            do {
                unsigned long long s0 = ldg_strong(gp);
                unsigned long long s1 = ldg_strong(gp + 1);
                unsigned long long s2 = ldg_strong(gp + 2);
                unsigned long long s3 = ldg_strong(gp + 3);
                if (!(done & 1u) && (unsigned)(s0 >> 32) == tg) {
                    shb[tid * 4 + 0] = __uint_as_float((unsigned)s0); done |= 1u;
                }
                if (!(done & 2u) && (unsigned)(s1 >> 32) == tg) {
                    shb[tid * 4 + 1] = __uint_as_float((unsigned)s1); done |= 2u;
                }
                if (!(done & 4u) && (unsigned)(s2 >> 32) == tg) {
                    shb[tid * 4 + 2] = __uint_as_float((unsigned)s2); done |= 4u;
                }
                if (!(done & 8u) && (unsigned)(s3 >> 32) == tg) {
                    shb[tid * 4 + 3] = __uint_as_float((unsigned)s3); done |= 8u;
                }
            } while (done != 15u);
        }
        __syncthreads();

        // Phase B: 4 gate dots + full-butterfly reduce (all lanes get sums).
        float a0 = 0.f, a1 = 0.f, a2 = 0.f, a3 = 0.f;
        #pragma unroll
        for (int m = 0; m < 16; m++) {
            float h = shb[lane + 32 * m];
            a0 = fmaf(w[0][m], h, a0);
            a1 = fmaf(w[1][m], h, a1);
            a2 = fmaf(w[2][m], h, a2);
            a3 = fmaf(w[3][m], h, a3);
        }
        #pragma unroll
        for (int off = 16; off; off >>= 1) {
            a0 += __shfl_xor_sync(0xffffffffu, a0, off);
            a1 += __shfl_xor_sync(0xffffffffu, a1, off);
            a2 += __shfl_xor_sync(0xffffffffu, a2, off);
            a3 += __shfl_xor_sync(0xffffffffu, a3, off);
        }

        // All lanes redundantly compute gates (same inputs, deterministic).
        float gi = fsigm(a0 + xg0);
        float gf = fsigm(a1 + xg1);
        float gg = ftanh(a2 + xg2);
        float go = fsigm(a3 + xg3);
        c_state = gf * c_state + gi * gg;
        float hn = go * ftanh(c_state);

        // Publish: lanes 0..NREP-1 store the replicas in parallel.
        unsigned long long pk =
            ((unsigned long long)(tg + 1u) << 32) |
            (unsigned long long)__float_as_uint(hn);
        if (lane < NREP)
            stg_strong(&g_hp[t & (NBUF - 1)][lane][unit], pk);
    }

    // ---- fused finalize: attention head + outputs (CTAs 0..63 only) ----
    const int o = blockIdx.x;
    if (o < 64) {
        const unsigned tgF = (unsigned)SEQ;          // tag 1024 = h_1023
        float* shf = sh_h[0];                        // free: last read at t=1022
        const unsigned long long* gp =
            &g_hp[(SEQ + NBUF - 1) & (NBUF - 1)][rep][tid * 4];
        #pragma unroll
        for (int i = 0; i < 4; i++) {
            unsigned long long p = ldg_strong(gp + i);
            while ((unsigned)(p >> 32) != tgF) p = ldg_strong(gp + i);
            shf[tid * 4 + i] = __uint_as_float((unsigned)p);
        }
        __syncthreads();

        const float* aw = attn_w + o * HID + tid * 4;
        float s = shf[tid * 4 + 0] * aw[0]
                + shf[tid * 4 + 1] * aw[1]
                + shf[tid * 4 + 2] * aw[2]
                + shf[tid * 4 + 3] * aw[3];
        #pragma unroll
        for (int off = 16; off; off >>= 1)
            s += __shfl_xor_sync(0xffffffffu, s, off);
        if (lane == 0) red[warp] = s;
        __syncthreads();
        if (tid == 0) {
            float tot = red[0] + red[1] + red[2] + red[3];
            red[0] = 1.0f / (1.0f + expf(-(tot + attn_b[o])));
        }
        __syncthreads();
        float a = red[0];
        #pragma unroll
        for (int p = tid; p < 1024; p += SCAN_THREADS)
            out[o * 1024 + p] = a;                   // x_attention broadcast
        if (o == 0)
            for (int k = tid; k < HID; k += SCAN_THREADS)
                out[65536 + k] = shf[k];             // x_instr_rep
    }
}

// ---------------- launch -------------------------------------------------
extern "C" void kernel_launch(void* const* d_in, const int* in_sizes, int n_in,
                              void* d_out, int out_size)
{
    const int*   tok    = (const int*)  d_in[0];
    const float* emb    = (const float*)d_in[1];
    const float* w_ih   = (const float*)d_in[2];
    const float* w_hh   = (const float*)d_in[3];
    const float* b_ih   = (const float*)d_in[4];
    const float* b_hh   = (const float*)d_in[5];
    const float* attn_w = (const float*)d_in[6];
    const float* attn_b = (const float*)d_in[7];
    float* out = (float*)d_out;

    dim3 gg(GATES / 64, SEQ / 64);           // 32 x 16 blocks
    xgates_gemm<<<gg, 256>>>(tok, emb, w_ih, b_ih, b_hh);
    lstm_scan<<<G_CTAS, SCAN_THREADS>>>(w_hh, attn_w, attn_b, out);
}